// round 10
// baseline (speedup 1.0000x reference)
#include <cuda_runtime.h>
#include <cuda_bf16.h>
#include <cstdint>

// Problem constants
#define S_   16
#define P_   32
#define B_   512
#define H_   64
#define D1_  8192
#define BOT_ 1024
#define RTOT (S_*P_*P_)

// GEMM-2 tiling
#define BM   64
#define BN   128
#define BK   32
#define NCHUNK (D1_/BK)     // 256
#define NSTAGE 4

// ---------------- device scratch (allocation-free) ----------------
__device__ __align__(256) float g_G[B_ * D1_];               // 16 MB fp32
__device__ __align__(256) float g_M[2 * D1_];
__device__ __align__(256) __nv_bfloat16 g_W2T_h[BOT_ * D1_]; // W2^T hi  [n][k]
__device__ __align__(256) __nv_bfloat16 g_W2T_l[BOT_ * D1_]; // W2^T lo  [n][k]

// ---------------- PTX helpers ----------------
__device__ __forceinline__ uint32_t smem_u32(const void* p) {
    uint32_t a;
    asm("{ .reg .u64 t; cvta.to.shared.u64 t, %1; cvt.u32.u64 %0, t; }" : "=r"(a) : "l"(p));
    return a;
}
// 64-byte-row swizzle for B tiles (BK=32)
#define SWZ64(row, kbyte) ((row) * 64 + ((kbyte) ^ (((row) & 6) << 3)))

__device__ __forceinline__ void mma16816(float* c, const uint32_t* a, const uint32_t* b) {
    asm volatile(
        "mma.sync.aligned.m16n8k16.row.col.f32.bf16.bf16.f32 "
        "{%0,%1,%2,%3}, {%4,%5,%6,%7}, {%8,%9}, {%0,%1,%2,%3};"
        : "+f"(c[0]), "+f"(c[1]), "+f"(c[2]), "+f"(c[3])
        : "r"(a[0]), "r"(a[1]), "r"(a[2]), "r"(a[3]), "r"(b[0]), "r"(b[1]));
}
__device__ __forceinline__ void ldsm4(uint32_t* r, uint32_t addr) {
    asm volatile("ldmatrix.sync.aligned.m8n8.x4.shared.b16 {%0,%1,%2,%3}, [%4];"
        : "=r"(r[0]), "=r"(r[1]), "=r"(r[2]), "=r"(r[3]) : "r"(addr));
}
#define CP16(dst, src) asm volatile("cp.async.cg.shared.global [%0], [%1], 16;" :: "r"(dst), "l"(src))
#define CP_COMMIT()    asm volatile("cp.async.commit_group;")
#define CP_WAIT2()     asm volatile("cp.async.wait_group 2;")

__device__ __forceinline__ unsigned long long lds_u64(uint32_t addr) {
    unsigned long long v;
    asm volatile("ld.shared.b64 %0, [%1];" : "=l"(v) : "r"(addr));
    return v;
}
__device__ __forceinline__ unsigned long long pack2f(float x, float y) {
    unsigned long long r;
    asm("mov.b64 %0, {%1, %2};" : "=l"(r) : "f"(x), "f"(y));
    return r;
}

// hi/lo bf16 split of relu(rx*M0 + ry*M1 + G), packed-f32x2 math
__device__ __forceinline__ void mk_frag2(unsigned long long m0p, unsigned long long m1p,
                                         unsigned long long gp,
                                         unsigned long long rxp, unsigned long long ryp,
                                         uint32_t& hi, uint32_t& lo) {
    unsigned long long acc = gp;
    asm("fma.rn.f32x2 %0, %1, %2, %0;" : "+l"(acc) : "l"(ryp), "l"(m1p));
    asm("fma.rn.f32x2 %0, %1, %2, %0;" : "+l"(acc) : "l"(rxp), "l"(m0p));
    float v0, v1;
    asm("mov.b64 {%0, %1}, %2;" : "=f"(v0), "=f"(v1) : "l"(acc));
    v0 = fmaxf(v0, 0.f);
    v1 = fmaxf(v1, 0.f);
    __nv_bfloat162 h = __floats2bfloat162_rn(v0, v1);
    uint32_t hb = *(uint32_t*)&h;
    float h0 = __uint_as_float(hb << 16);
    float h1 = __uint_as_float(hb & 0xffff0000u);
    __nv_bfloat162 l = __floats2bfloat162_rn(v0 - h0, v1 - h1);
    hi = hb;
    lo = *(uint32_t*)&l;
}

// ---------------- Prep kernels ----------------
__global__ __launch_bounds__(256) void kern_M(const float* __restrict__ Wsp,
                                              const float* __restrict__ W1) {
    int d = blockIdx.x * 256 + threadIdx.x;
    float m0 = 0.f, m1 = 0.f;
    #pragma unroll 8
    for (int j = 0; j < 64; j++) {
        float w = W1[j * D1_ + d];
        m0 = fmaf(Wsp[j],      w, m0);
        m1 = fmaf(Wsp[64 + j], w, m1);
    }
    g_M[d]       = m0;
    g_M[D1_ + d] = m1;
}

__global__ __launch_bounds__(256) void kern_G(const float* __restrict__ h,
                                              const float* __restrict__ b_sp,
                                              const float* __restrict__ W1,
                                              const float* __restrict__ b1) {
    __shared__ float xs[8][128];
    const int tid  = threadIdx.x;
    const int col  = blockIdx.x * 256 + tid;
    const int row0 = blockIdx.y * 8;
    for (int e = tid; e < 8 * 128; e += 256) {
        int rr = e >> 7, j = e & 127;
        xs[rr][j] = (j < 64) ? b_sp[j] : h[(row0 + rr) * H_ + (j - 64)];
    }
    __syncthreads();
    float acc[8];
    float bb = b1[col];
    #pragma unroll
    for (int r = 0; r < 8; r++) acc[r] = bb;
    #pragma unroll 4
    for (int k = 0; k < 128; k++) {
        float w = W1[k * D1_ + col];
        #pragma unroll
        for (int r = 0; r < 8; r++) acc[r] = fmaf(xs[r][k], w, acc[r]);
    }
    #pragma unroll
    for (int r = 0; r < 8; r++) g_G[(row0 + r) * D1_ + col] = acc[r];
}

__global__ __launch_bounds__(256) void kern_W2T(const float* __restrict__ W2) {
    __shared__ float tile[32][33];
    const int tx = threadIdx.x, ty = threadIdx.y;
    const int n0 = blockIdx.x * 32, k0 = blockIdx.y * 32;
    #pragma unroll
    for (int r = 0; r < 4; r++)
        tile[ty + r * 8][tx] = W2[(k0 + ty + r * 8) * BOT_ + n0 + tx];
    __syncthreads();
    #pragma unroll
    for (int r = 0; r < 4; r++) {
        float v = tile[tx][ty + r * 8];
        __nv_bfloat16 hi = __float2bfloat16(v);
        __nv_bfloat16 lo = __float2bfloat16(v - __bfloat162float(hi));
        int o = (n0 + ty + r * 8) * D1_ + k0 + tx;
        g_W2T_h[o] = hi;
        g_W2T_l[o] = lo;
    }
}

// ---------------- Main kernel ----------------
// Per buffer: Bh 8K | Bl 8K | G 32x160B | M 2x160B  -> 22528 (1K aligned)
#define OFF_BLO   8192
#define OFF_G     16384
#define OFF_M     21504
#define BUF_STRIDE 22528
#define SMEM_BYTES (NSTAGE * BUF_STRIDE)   // 90112

__device__ __forceinline__ void stage_chunk(int k0, uint32_t tb, int t, int n0,
                                            int pedbase) {
    // B hi/lo: 128 n-rows x 4 x 16B segs (64B rows, SWZ64)
    #pragma unroll
    for (int i = 0; i < 2; i++) {
        int idx = t + i * 256;
        int n = idx >> 2, seg = idx & 3;
        int sw = SWZ64(n, seg * 16);
        const size_t off = (size_t)(n0 + n) * D1_ + k0 + seg * 8;
        CP16(tb + sw, g_W2T_h + off);
        CP16(tb + OFF_BLO + sw, g_W2T_l + off);
    }
    // G: 32 b-rows x 8 x 16B into 160B-stride rows
    {
        int b = t >> 3, seg = t & 7;
        CP16(tb + OFF_G + b * 160 + seg * 16,
             g_G + (size_t)(pedbase + b) * D1_ + k0 + seg * 4);
    }
    // M: 2 x 32 floats
    if (t < 16) {
        int half = t >> 3, seg = t & 7;
        CP16(tb + OFF_M + half * 160 + seg * 16, g_M + half * D1_ + k0 + seg * 4);
    }
}

__global__ __launch_bounds__(256, 2)
void kern_main_mma(const float* __restrict__ end_pos,
                   const float* __restrict__ b2,
                   float* __restrict__ out) {
    extern __shared__ __align__(1024) char smem[];
    const uint32_t sb = smem_u32(smem);
    const int t = threadIdx.x;
    const int lane = t & 31, wid = t >> 5;
    const int wm = wid >> 1, wn = wid & 1;        // 4 m-warps x 2 n-warps
    const int n0 = blockIdx.x * BN;
    const int r0 = blockIdx.y * BM;
    const int pedbase = (r0 >> 10) << 5;          // scene * 32

    // per-thread rel-pos: warp rows = wm*16..+15; b = (wm&1)*16 + g4 (+8)
    const int a_idx = ((blockIdx.y * 2) & 31) + (wm >> 1);
    const float pax = end_pos[(pedbase + a_idx) * 2 + 0];
    const float pay = end_pos[(pedbase + a_idx) * 2 + 1];
    const int g4 = lane >> 2;
    const int b0r = (wm & 1) * 16 + g4;
    const int b1r = b0r + 8;
    unsigned long long rxp0, ryp0, rxp1, ryp1;
    {
        float px = end_pos[(pedbase + b0r) * 2 + 0], py = end_pos[(pedbase + b0r) * 2 + 1];
        float rx = fminf(fmaxf(px - pax, -1.f), 1.f);
        float ry = fminf(fmaxf(py - pay, -1.f), 1.f);
        rxp0 = pack2f(rx, rx); ryp0 = pack2f(ry, ry);
        px = end_pos[(pedbase + b1r) * 2 + 0]; py = end_pos[(pedbase + b1r) * 2 + 1];
        rx = fminf(fmaxf(px - pax, -1.f), 1.f);
        ry = fminf(fmaxf(py - pay, -1.f), 1.f);
        rxp1 = pack2f(rx, rx); ryp1 = pack2f(ry, ry);
    }
    const uint32_t gOff0 = OFF_G + b0r * 160;
    const uint32_t gOff1 = OFF_G + b1r * 160;

    // B ldmatrix lane addressing
    const int bRow   = wn * 64 + (lane & 7) + ((lane >> 4) & 1) * 8;
    const int bKhalf = (lane >> 3) & 1;
    const int kq2    = (lane & 3) * 2;           // A-fragment k pair base

    float c[8][4];
    #pragma unroll
    for (int nt = 0; nt < 8; nt++)
        #pragma unroll
        for (int q = 0; q < 4; q++) c[nt][q] = 0.f;

    // prologue: stage chunks 0..2
    stage_chunk(0,       sb,                  t, n0, pedbase); CP_COMMIT();
    stage_chunk(BK,      sb + BUF_STRIDE,     t, n0, pedbase); CP_COMMIT();
    stage_chunk(2 * BK,  sb + 2 * BUF_STRIDE, t, n0, pedbase); CP_COMMIT();

    for (int ch = 0; ch < NCHUNK; ch++) {
        const uint32_t tb = sb + (ch & 3) * BUF_STRIDE;

        CP_WAIT2();          // stage(ch) complete (newest 2 groups may be in flight)
        __syncthreads();     // all warps done with MMA(ch-1); staging visible

        #pragma unroll
        for (int s = 0; s < 2; s++) {
            const int kk = s * 16 + kq2;          // local k (floats) 0..31
            // M pairs (packed u64 loads)
            unsigned long long m0a = lds_u64(tb + OFF_M + kk * 4);
            unsigned long long m0b = lds_u64(tb + OFF_M + kk * 4 + 32);
            unsigned long long m1a = lds_u64(tb + OFF_M + 160 + kk * 4);
            unsigned long long m1b = lds_u64(tb + OFF_M + 160 + kk * 4 + 32);

            // B fragments (hi/lo)
            uint32_t bh[4][4], bl[4][4];
            const int kbB = s * 32 + bKhalf * 16;
            #pragma unroll
            for (int p = 0; p < 4; p++) {
                int row = bRow + p * 16;
                uint32_t bd = tb + SWZ64(row, kbB);
                ldsm4(bh[p], bd);
                ldsm4(bl[p], bd + OFF_BLO);
            }

            // A fragments built in registers
            unsigned long long g0a = lds_u64(tb + gOff0 + kk * 4);
            unsigned long long g1a = lds_u64(tb + gOff1 + kk * 4);
            unsigned long long g0b = lds_u64(tb + gOff0 + kk * 4 + 32);
            unsigned long long g1b = lds_u64(tb + gOff1 + kk * 4 + 32);
            uint32_t ah[4], al[4];
            mk_frag2(m0a, m1a, g0a, rxp0, ryp0, ah[0], al[0]);
            mk_frag2(m0a, m1a, g1a, rxp1, ryp1, ah[1], al[1]);
            mk_frag2(m0b, m1b, g0b, rxp0, ryp0, ah[2], al[2]);
            mk_frag2(m0b, m1b, g1b, rxp1, ryp1, ah[3], al[3]);

            #pragma unroll
            for (int nt = 0; nt < 8; nt++) {
                const uint32_t* BH = &bh[nt >> 1][(nt & 1) * 2];
                const uint32_t* BL = &bl[nt >> 1][(nt & 1) * 2];
                mma16816(c[nt], ah, BH);
                mma16816(c[nt], ah, BL);
                mma16816(c[nt], al, BH);
            }
        }

        // stage chunk ch+3 (or empty-commit to keep group accounting uniform)
        if (ch + 3 < NCHUNK)
            stage_chunk((ch + 3) * BK, sb + ((ch + 3) & 3) * BUF_STRIDE, t, n0, pedbase);
        CP_COMMIT();
    }

    // ---- epilogue ----
    float* red = (float*)smem;          // [4][128] floats, reuses buffer 0
    #pragma unroll
    for (int nt = 0; nt < 8; nt++) {
        #pragma unroll
        for (int j = 0; j < 2; j++) {
            float m = fmaxf(c[nt][j], c[nt][j + 2]);
            m = fmaxf(m, __shfl_xor_sync(0xffffffffu, m, 4));
            m = fmaxf(m, __shfl_xor_sync(0xffffffffu, m, 8));
            m = fmaxf(m, __shfl_xor_sync(0xffffffffu, m, 16));
            if (lane < 4)
                red[wm * 128 + wn * 64 + nt * 8 + lane * 2 + j] = m;
        }
    }
    __syncthreads();
    {
        const int a_local = t >> 7;          // 0..1
        const int col = t & 127;
        float m = fmaxf(red[(a_local * 2) * 128 + col],
                        red[(a_local * 2 + 1) * 128 + col]);
        const int ped = blockIdx.y * 2 + a_local;
        const int n = n0 + col;
        out[(size_t)ped * BOT_ + n] = fmaxf(m + b2[n], 0.f);
    }
}

// ---------------------------------------------------------------------------
extern "C" void kernel_launch(void* const* d_in, const int* in_sizes, int n_in,
                              void* d_out, int out_size) {
    const float* h_states = (const float*)d_in[0];
    const float* end_pos  = (const float*)d_in[1];
    const float* W_sp = (const float*)d_in[4];
    const float* b_sp = (const float*)d_in[5];
    const float* W1   = (const float*)d_in[6];
    const float* b1   = (const float*)d_in[7];
    const float* W2   = (const float*)d_in[8];
    const float* b2   = (const float*)d_in[9];
    float* out = (float*)d_out;

    cudaFuncSetAttribute(kern_main_mma, cudaFuncAttributeMaxDynamicSharedMemorySize, SMEM_BYTES);

    kern_M<<<D1_ / 256, 256>>>(W_sp, W1);
    kern_G<<<dim3(D1_ / 256, B_ / 8), 256>>>(h_states, b_sp, W1, b1);
    kern_W2T<<<dim3(BOT_ / 32, D1_ / 32), dim3(32, 8)>>>(W2);
    kern_main_mma<<<dim3(BOT_ / BN, RTOT / BM), 256, SMEM_BYTES>>>(end_pos, b2, out);
}

// round 11
// speedup vs baseline: 1.2369x; 1.2369x over previous
#include <cuda_runtime.h>
#include <cuda_fp16.h>
#include <cstdint>

// Problem constants
#define S_   16
#define P_   32
#define B_   512
#define H_   64
#define D1_  8192
#define BOT_ 1024
#define RTOT (S_*P_*P_)

// GEMM-2 tiling (R7 best config)
#define BM   64
#define BN   128
#define BK   64
#define NCHUNK (D1_/BK)     // 128

// W2 pre-scale so fp16-lo terms stay normal; undone in epilogue
#define W2SCALE 256.0f
#define INV_W2SCALE (1.0f/256.0f)

// ---------------- device scratch (allocation-free) ----------------
__device__ __align__(256) float g_G[B_ * D1_];        // 16 MB fp32
__device__ __align__(256) float g_M[2 * D1_];
__device__ __align__(256) __half g_W2T_h[BOT_ * D1_]; // W2^T*256 hi  [n][k]
__device__ __align__(256) __half g_W2T_l[BOT_ * D1_]; // W2^T*256 lo  [n][k]

// ---------------- PTX helpers ----------------
__device__ __forceinline__ uint32_t smem_u32(const void* p) {
    uint32_t a;
    asm("{ .reg .u64 t; cvta.to.shared.u64 t, %1; cvt.u32.u64 %0, t; }" : "=r"(a) : "l"(p));
    return a;
}
__device__ __forceinline__ void mma16816(float* c, const uint32_t* a, const uint32_t* b) {
    asm volatile(
        "mma.sync.aligned.m16n8k16.row.col.f32.f16.f16.f32 "
        "{%0,%1,%2,%3}, {%4,%5,%6,%7}, {%8,%9}, {%0,%1,%2,%3};"
        : "+f"(c[0]), "+f"(c[1]), "+f"(c[2]), "+f"(c[3])
        : "r"(a[0]), "r"(a[1]), "r"(a[2]), "r"(a[3]), "r"(b[0]), "r"(b[1]));
}
__device__ __forceinline__ void ldsm4(uint32_t* r, uint32_t addr) {
    asm volatile("ldmatrix.sync.aligned.m8n8.x4.shared.b16 {%0,%1,%2,%3}, [%4];"
        : "=r"(r[0]), "=r"(r[1]), "=r"(r[2]), "=r"(r[3]) : "r"(addr));
}
#define CP16(dst, src) asm volatile("cp.async.cg.shared.global [%0], [%1], 16;" :: "r"(dst), "l"(src))
#define CP_COMMIT()    asm volatile("cp.async.commit_group;")
#define CP_WAIT0()     asm volatile("cp.async.wait_group 0;")

__device__ __forceinline__ unsigned long long lds_u64(uint32_t addr) {
    unsigned long long v;
    asm volatile("ld.shared.b64 %0, [%1];" : "=l"(v) : "r"(addr));
    return v;
}
__device__ __forceinline__ unsigned long long pack2f(float x, float y) {
    unsigned long long r;
    asm("mov.b64 %0, {%1, %2};" : "=l"(r) : "f"(x), "f"(y));
    return r;
}

// fp16x2 of relu(rx*M0 + ry*M1 + G), packed-f32x2 math
__device__ __forceinline__ uint32_t mk_fragh(unsigned long long m0p, unsigned long long m1p,
                                             unsigned long long gp,
                                             unsigned long long rxp, unsigned long long ryp) {
    unsigned long long acc = gp;
    asm("fma.rn.f32x2 %0, %1, %2, %0;" : "+l"(acc) : "l"(ryp), "l"(m1p));
    asm("fma.rn.f32x2 %0, %1, %2, %0;" : "+l"(acc) : "l"(rxp), "l"(m0p));
    float v0, v1;
    asm("mov.b64 {%0, %1}, %2;" : "=f"(v0), "=f"(v1) : "l"(acc));
    v0 = fmaxf(v0, 0.f);
    v1 = fmaxf(v1, 0.f);
    __half2 h = __floats2half2_rn(v0, v1);
    return *(uint32_t*)&h;
}

// ---------------- Prep kernels ----------------
__global__ __launch_bounds__(256) void kern_M(const float* __restrict__ Wsp,
                                              const float* __restrict__ W1) {
    int d = blockIdx.x * 256 + threadIdx.x;
    float m0 = 0.f, m1 = 0.f;
    #pragma unroll 8
    for (int j = 0; j < 64; j++) {
        float w = W1[j * D1_ + d];
        m0 = fmaf(Wsp[j],      w, m0);
        m1 = fmaf(Wsp[64 + j], w, m1);
    }
    g_M[d]       = m0;
    g_M[D1_ + d] = m1;
}

__global__ __launch_bounds__(256) void kern_G(const float* __restrict__ h,
                                              const float* __restrict__ b_sp,
                                              const float* __restrict__ W1,
                                              const float* __restrict__ b1) {
    __shared__ float xs[8][128];
    const int tid  = threadIdx.x;
    const int col  = blockIdx.x * 256 + tid;
    const int row0 = blockIdx.y * 8;
    for (int e = tid; e < 8 * 128; e += 256) {
        int rr = e >> 7, j = e & 127;
        xs[rr][j] = (j < 64) ? b_sp[j] : h[(row0 + rr) * H_ + (j - 64)];
    }
    __syncthreads();
    float acc[8];
    float bb = b1[col];
    #pragma unroll
    for (int r = 0; r < 8; r++) acc[r] = bb;
    #pragma unroll 4
    for (int k = 0; k < 128; k++) {
        float w = W1[k * D1_ + col];
        #pragma unroll
        for (int r = 0; r < 8; r++) acc[r] = fmaf(xs[r][k], w, acc[r]);
    }
    #pragma unroll
    for (int r = 0; r < 8; r++) g_G[(row0 + r) * D1_ + col] = acc[r];
}

// W2 [8192,1024] fp32 -> (W2^T * 256) hi/lo fp16 [1024,8192]
__global__ __launch_bounds__(256) void kern_W2T(const float* __restrict__ W2) {
    __shared__ float tile[32][33];
    const int tx = threadIdx.x, ty = threadIdx.y;
    const int n0 = blockIdx.x * 32, k0 = blockIdx.y * 32;
    #pragma unroll
    for (int r = 0; r < 4; r++)
        tile[ty + r * 8][tx] = W2[(k0 + ty + r * 8) * BOT_ + n0 + tx];
    __syncthreads();
    #pragma unroll
    for (int r = 0; r < 4; r++) {
        float v = tile[tx][ty + r * 8] * W2SCALE;
        __half hi = __float2half_rn(v);
        __half lo = __float2half_rn(v - __half2float(hi));
        int o = (n0 + ty + r * 8) * D1_ + k0 + tx;
        g_W2T_h[o] = hi;
        g_W2T_l[o] = lo;
    }
}

// ---------------- Main kernel ----------------
// Per buffer: Bh 16K | Bl 16K | G 32x288B | M 2x288B  -> 43008 B
#define OFF_BLO   16384
#define OFF_G     32768
#define OFF_M     41984
#define BUF_STRIDE 43008
#define SMEM_BYTES (2 * BUF_STRIDE)   // 86016

__device__ __forceinline__ void stage_chunk(int k0, uint32_t tb, int t, int n0,
                                            int pedbase) {
    // B hi/lo: 128 n-rows x 8 x 16B (SW128 swizzle on 128B rows)
    #pragma unroll
    for (int i = 0; i < 4; i++) {
        int idx = t + i * 256;
        int n = idx >> 3, seg = idx & 7;
        int sw = n * 128 + ((seg * 16) ^ ((n & 7) << 4));
        const size_t off = (size_t)(n0 + n) * D1_ + k0 + seg * 8;
        CP16(tb + sw, g_W2T_h + off);
        CP16(tb + OFF_BLO + sw, g_W2T_l + off);
    }
    // G: 32 b-rows x 16 x 16B into 288B-stride rows
    #pragma unroll
    for (int i = 0; i < 2; i++) {
        int idx = t + i * 256;
        int b = idx >> 4, seg = idx & 15;
        CP16(tb + OFF_G + b * 288 + seg * 16,
             g_G + (size_t)(pedbase + b) * D1_ + k0 + seg * 4);
    }
    // M: 2 x 64 floats
    if (t < 32) {
        int half = t >> 4, seg = t & 15;
        CP16(tb + OFF_M + half * 288 + seg * 16, g_M + half * D1_ + k0 + seg * 4);
    }
}

__global__ __launch_bounds__(256, 2)
void kern_main_mma(const float* __restrict__ end_pos,
                   const float* __restrict__ b2,
                   float* __restrict__ out) {
    extern __shared__ __align__(1024) char smem[];
    const uint32_t sb = smem_u32(smem);
    const int t = threadIdx.x;
    const int lane = t & 31, wid = t >> 5;
    const int wm = wid >> 1, wn = wid & 1;        // 4 m-warps x 2 n-warps
    const int n0 = blockIdx.x * BN;
    const int r0 = blockIdx.y * BM;
    const int pedbase = (r0 >> 10) << 5;          // scene * 32

    // per-thread rel-pos: warp rows = wm*16..+15; b = (wm&1)*16 + g4 (+8)
    const int a_idx = ((blockIdx.y * 2) & 31) + (wm >> 1);
    const float pax = end_pos[(pedbase + a_idx) * 2 + 0];
    const float pay = end_pos[(pedbase + a_idx) * 2 + 1];
    const int g4 = lane >> 2;
    const int b0r = (wm & 1) * 16 + g4;
    const int b1r = b0r + 8;
    unsigned long long rxp0, ryp0, rxp1, ryp1;
    {
        float px = end_pos[(pedbase + b0r) * 2 + 0], py = end_pos[(pedbase + b0r) * 2 + 1];
        float rx = fminf(fmaxf(px - pax, -1.f), 1.f);
        float ry = fminf(fmaxf(py - pay, -1.f), 1.f);
        rxp0 = pack2f(rx, rx); ryp0 = pack2f(ry, ry);
        px = end_pos[(pedbase + b1r) * 2 + 0]; py = end_pos[(pedbase + b1r) * 2 + 1];
        rx = fminf(fmaxf(px - pax, -1.f), 1.f);
        ry = fminf(fmaxf(py - pay, -1.f), 1.f);
        rxp1 = pack2f(rx, rx); ryp1 = pack2f(ry, ry);
    }
    const uint32_t gOff0 = OFF_G + b0r * 288;
    const uint32_t gOff1 = OFF_G + b1r * 288;

    // B ldmatrix lane addressing
    const int bRow   = wn * 64 + (lane & 7) + ((lane >> 4) & 1) * 8;
    const int bKhalf = (lane >> 3) & 1;
    const int kq2    = (lane & 3) * 2;           // A-fragment k pair base

    float c[8][4];
    #pragma unroll
    for (int nt = 0; nt < 8; nt++)
        #pragma unroll
        for (int q = 0; q < 4; q++) c[nt][q] = 0.f;

    // prologue
    stage_chunk(0, sb, t, n0, pedbase);
    CP_COMMIT(); CP_WAIT0();
    __syncthreads();

    for (int ch = 0; ch < NCHUNK; ch++) {
        const int buf = ch & 1;
        const uint32_t tb = sb + buf * BUF_STRIDE;

        if (ch + 1 < NCHUNK) {
            stage_chunk((ch + 1) * BK, sb + (buf ^ 1) * BUF_STRIDE, t, n0, pedbase);
            CP_COMMIT();
        }

        #pragma unroll
        for (int s = 0; s < 4; s++) {
            const int kk = s * 16 + kq2;          // local k (floats) 0..63
            // M pairs (packed u64 loads)
            unsigned long long m0a = lds_u64(tb + OFF_M + kk * 4);
            unsigned long long m0b = lds_u64(tb + OFF_M + kk * 4 + 32);
            unsigned long long m1a = lds_u64(tb + OFF_M + 288 + kk * 4);
            unsigned long long m1b = lds_u64(tb + OFF_M + 288 + kk * 4 + 32);

            // B fragments (hi/lo)
            uint32_t bh[4][4], bl[4][4];
            const int kbB = s * 32 + bKhalf * 16;
            #pragma unroll
            for (int p = 0; p < 4; p++) {
                int row = bRow + p * 16;
                uint32_t bd = tb + row * 128 + (kbB ^ ((row & 7) << 4));
                ldsm4(bh[p], bd);
                ldsm4(bl[p], bd + OFF_BLO);
            }

            // A fragments built in registers (single fp16)
            unsigned long long g0a = lds_u64(tb + gOff0 + kk * 4);
            unsigned long long g1a = lds_u64(tb + gOff1 + kk * 4);
            unsigned long long g0b = lds_u64(tb + gOff0 + kk * 4 + 32);
            unsigned long long g1b = lds_u64(tb + gOff1 + kk * 4 + 32);
            uint32_t ah[4];
            ah[0] = mk_fragh(m0a, m1a, g0a, rxp0, ryp0);
            ah[1] = mk_fragh(m0a, m1a, g1a, rxp1, ryp1);
            ah[2] = mk_fragh(m0b, m1b, g0b, rxp0, ryp0);
            ah[3] = mk_fragh(m0b, m1b, g1b, rxp1, ryp1);

            #pragma unroll
            for (int nt = 0; nt < 8; nt++) {
                const uint32_t* BH = &bh[nt >> 1][(nt & 1) * 2];
                const uint32_t* BL = &bl[nt >> 1][(nt & 1) * 2];
                mma16816(c[nt], ah, BH);
                mma16816(c[nt], ah, BL);
            }
        }

        if (ch + 1 < NCHUNK) {
            CP_WAIT0();
            __syncthreads();
        }
    }

    // ---- epilogue ----
    // warp-local max over its 16 b-rows, then cross-warp pair via smem; undo W2SCALE
    float* red = (float*)smem;          // [4][128] floats, reuses buffer 0
    #pragma unroll
    for (int nt = 0; nt < 8; nt++) {
        #pragma unroll
        for (int j = 0; j < 2; j++) {
            float m = fmaxf(c[nt][j], c[nt][j + 2]);
            m = fmaxf(m, __shfl_xor_sync(0xffffffffu, m, 4));
            m = fmaxf(m, __shfl_xor_sync(0xffffffffu, m, 8));
            m = fmaxf(m, __shfl_xor_sync(0xffffffffu, m, 16));
            if (lane < 4)
                red[wm * 128 + wn * 64 + nt * 8 + lane * 2 + j] = m;
        }
    }
    __syncthreads();
    {
        const int a_local = t >> 7;          // 0..1
        const int col = t & 127;
        float m = fmaxf(red[(a_local * 2) * 128 + col],
                        red[(a_local * 2 + 1) * 128 + col]);
        const int ped = blockIdx.y * 2 + a_local;
        const int n = n0 + col;
        out[(size_t)ped * BOT_ + n] = fmaxf(fmaf(m, INV_W2SCALE, b2[n]), 0.f);
    }
}

// ---------------------------------------------------------------------------
extern "C" void kernel_launch(void* const* d_in, const int* in_sizes, int n_in,
                              void* d_out, int out_size) {
    const float* h_states = (const float*)d_in[0];
    const float* end_pos  = (const float*)d_in[1];
    const float* W_sp = (const float*)d_in[4];
    const float* b_sp = (const float*)d_in[5];
    const float* W1   = (const float*)d_in[6];
    const float* b1   = (const float*)d_in[7];
    const float* W2   = (const float*)d_in[8];
    const float* b2   = (const float*)d_in[9];
    float* out = (float*)d_out;

    cudaFuncSetAttribute(kern_main_mma, cudaFuncAttributeMaxDynamicSharedMemorySize, SMEM_BYTES);

    kern_M<<<D1_ / 256, 256>>>(W_sp, W1);
    kern_G<<<dim3(D1_ / 256, B_ / 8), 256>>>(h_states, b_sp, W1, b1);
    kern_W2T<<<dim3(BOT_ / 32, D1_ / 32), dim3(32, 8)>>>(W2);
    kern_main_mma<<<dim3(BOT_ / BN, RTOT / BM), 256, SMEM_BYTES>>>(end_pos, b2, out);
}

// round 12
// speedup vs baseline: 1.8835x; 1.5228x over previous
#include <cuda_runtime.h>
#include <cuda_fp16.h>
#include <cstdint>

// Problem constants
#define S_   16
#define P_   32
#define B_   512
#define H_   64
#define D1_  8192
#define BOT_ 1024
#define RTOT (S_*P_*P_)

// GEMM-2 tiling
#define BM   64
#define BN   128
#define BK   64
#define NCHUNK (D1_/BK)     // 128

// ---------------- device scratch (allocation-free) ----------------
__device__ __align__(256) float g_G[B_ * D1_];        // 16 MB fp32
__device__ __align__(256) float g_M[2 * D1_];
__device__ __align__(256) __half g_W2T_h[BOT_ * D1_]; // W2^T fp16  [n][k]

// ---------------- PTX helpers ----------------
__device__ __forceinline__ uint32_t smem_u32(const void* p) {
    uint32_t a;
    asm("{ .reg .u64 t; cvta.to.shared.u64 t, %1; cvt.u32.u64 %0, t; }" : "=r"(a) : "l"(p));
    return a;
}
__device__ __forceinline__ void mma16816(float* c, const uint32_t* a, const uint32_t* b) {
    asm volatile(
        "mma.sync.aligned.m16n8k16.row.col.f32.f16.f16.f32 "
        "{%0,%1,%2,%3}, {%4,%5,%6,%7}, {%8,%9}, {%0,%1,%2,%3};"
        : "+f"(c[0]), "+f"(c[1]), "+f"(c[2]), "+f"(c[3])
        : "r"(a[0]), "r"(a[1]), "r"(a[2]), "r"(a[3]), "r"(b[0]), "r"(b[1]));
}
__device__ __forceinline__ void ldsm4(uint32_t* r, uint32_t addr) {
    asm volatile("ldmatrix.sync.aligned.m8n8.x4.shared.b16 {%0,%1,%2,%3}, [%4];"
        : "=r"(r[0]), "=r"(r[1]), "=r"(r[2]), "=r"(r[3]) : "r"(addr));
}
#define CP16(dst, src) asm volatile("cp.async.cg.shared.global [%0], [%1], 16;" :: "r"(dst), "l"(src))
#define CP_COMMIT()    asm volatile("cp.async.commit_group;")
#define CP_WAIT0()     asm volatile("cp.async.wait_group 0;")

__device__ __forceinline__ unsigned long long lds_u64(uint32_t addr) {
    unsigned long long v;
    asm volatile("ld.shared.b64 %0, [%1];" : "=l"(v) : "r"(addr));
    return v;
}
__device__ __forceinline__ unsigned long long pack2f(float x, float y) {
    unsigned long long r;
    asm("mov.b64 %0, {%1, %2};" : "=l"(r) : "f"(x), "f"(y));
    return r;
}

// fp16x2 of relu(rx*M0 + ry*M1 + G), packed-f32x2 math
__device__ __forceinline__ uint32_t mk_fragh(unsigned long long m0p, unsigned long long m1p,
                                             unsigned long long gp,
                                             unsigned long long rxp, unsigned long long ryp) {
    unsigned long long acc = gp;
    asm("fma.rn.f32x2 %0, %1, %2, %0;" : "+l"(acc) : "l"(ryp), "l"(m1p));
    asm("fma.rn.f32x2 %0, %1, %2, %0;" : "+l"(acc) : "l"(rxp), "l"(m0p));
    float v0, v1;
    asm("mov.b64 {%0, %1}, %2;" : "=f"(v0), "=f"(v1) : "l"(acc));
    v0 = fmaxf(v0, 0.f);
    v1 = fmaxf(v1, 0.f);
    __half2 h = __floats2half2_rn(v0, v1);
    return *(uint32_t*)&h;
}

// ---------------- Prep kernels ----------------
__global__ __launch_bounds__(256) void kern_M(const float* __restrict__ Wsp,
                                              const float* __restrict__ W1) {
    int d = blockIdx.x * 256 + threadIdx.x;
    float m0 = 0.f, m1 = 0.f;
    #pragma unroll 8
    for (int j = 0; j < 64; j++) {
        float w = W1[j * D1_ + d];
        m0 = fmaf(Wsp[j],      w, m0);
        m1 = fmaf(Wsp[64 + j], w, m1);
    }
    g_M[d]       = m0;
    g_M[D1_ + d] = m1;
}

__global__ __launch_bounds__(256) void kern_G(const float* __restrict__ h,
                                              const float* __restrict__ b_sp,
                                              const float* __restrict__ W1,
                                              const float* __restrict__ b1) {
    __shared__ float xs[8][128];
    const int tid  = threadIdx.x;
    const int col  = blockIdx.x * 256 + tid;
    const int row0 = blockIdx.y * 8;
    for (int e = tid; e < 8 * 128; e += 256) {
        int rr = e >> 7, j = e & 127;
        xs[rr][j] = (j < 64) ? b_sp[j] : h[(row0 + rr) * H_ + (j - 64)];
    }
    __syncthreads();
    float acc[8];
    float bb = b1[col];
    #pragma unroll
    for (int r = 0; r < 8; r++) acc[r] = bb;
    #pragma unroll 4
    for (int k = 0; k < 128; k++) {
        float w = W1[k * D1_ + col];
        #pragma unroll
        for (int r = 0; r < 8; r++) acc[r] = fmaf(xs[r][k], w, acc[r]);
    }
    #pragma unroll
    for (int r = 0; r < 8; r++) g_G[(row0 + r) * D1_ + col] = acc[r];
}

// W2 [8192,1024] fp32 -> W2^T fp16 [1024,8192]
__global__ __launch_bounds__(256) void kern_W2T(const float* __restrict__ W2) {
    __shared__ float tile[32][33];
    const int tx = threadIdx.x, ty = threadIdx.y;
    const int n0 = blockIdx.x * 32, k0 = blockIdx.y * 32;
    #pragma unroll
    for (int r = 0; r < 4; r++)
        tile[ty + r * 8][tx] = W2[(k0 + ty + r * 8) * BOT_ + n0 + tx];
    __syncthreads();
    #pragma unroll
    for (int r = 0; r < 4; r++) {
        float v = tile[tx][ty + r * 8];
        g_W2T_h[(n0 + ty + r * 8) * D1_ + k0 + tx] = __float2half_rn(v);
    }
}

// ---------------- Main kernel ----------------
// Per buffer: Bh 16K | G 32x288B | M 2x288B  -> 26624 B (1K aligned)
#define OFF_G     16384
#define OFF_M     25600
#define BUF_STRIDE 26624
#define SMEM_BYTES (2 * BUF_STRIDE)   // 53248

__device__ __forceinline__ void stage_chunk(int k0, uint32_t tb, int t, int n0,
                                            int pedbase) {
    // B hi: 128 n-rows x 8 x 16B (SW128 swizzle on 128B rows)
    #pragma unroll
    for (int i = 0; i < 4; i++) {
        int idx = t + i * 256;
        int n = idx >> 3, seg = idx & 7;
        int sw = n * 128 + ((seg * 16) ^ ((n & 7) << 4));
        CP16(tb + sw, g_W2T_h + (size_t)(n0 + n) * D1_ + k0 + seg * 8);
    }
    // G: 32 b-rows x 16 x 16B into 288B-stride rows
    #pragma unroll
    for (int i = 0; i < 2; i++) {
        int idx = t + i * 256;
        int b = idx >> 4, seg = idx & 15;
        CP16(tb + OFF_G + b * 288 + seg * 16,
             g_G + (size_t)(pedbase + b) * D1_ + k0 + seg * 4);
    }
    // M: 2 x 64 floats
    if (t < 32) {
        int half = t >> 4, seg = t & 15;
        CP16(tb + OFF_M + half * 288 + seg * 16, g_M + half * D1_ + k0 + seg * 4);
    }
}

__global__ __launch_bounds__(256, 2)
void kern_main_mma(const float* __restrict__ end_pos,
                   const float* __restrict__ b2,
                   float* __restrict__ out) {
    extern __shared__ __align__(1024) char smem[];
    const uint32_t sb = smem_u32(smem);
    const int t = threadIdx.x;
    const int lane = t & 31, wid = t >> 5;
    const int wm = wid >> 1, wn = wid & 1;        // 4 m-warps x 2 n-warps
    const int n0 = blockIdx.x * BN;
    const int r0 = blockIdx.y * BM;
    const int pedbase = (r0 >> 10) << 5;          // scene * 32

    // per-thread rel-pos: warp rows = wm*16..+15; b = (wm&1)*16 + g4 (+8)
    const int a_idx = ((blockIdx.y * 2) & 31) + (wm >> 1);
    const float pax = end_pos[(pedbase + a_idx) * 2 + 0];
    const float pay = end_pos[(pedbase + a_idx) * 2 + 1];
    const int g4 = lane >> 2;
    const int b0r = (wm & 1) * 16 + g4;
    const int b1r = b0r + 8;
    unsigned long long rxp0, ryp0, rxp1, ryp1;
    {
        float px = end_pos[(pedbase + b0r) * 2 + 0], py = end_pos[(pedbase + b0r) * 2 + 1];
        float rx = fminf(fmaxf(px - pax, -1.f), 1.f);
        float ry = fminf(fmaxf(py - pay, -1.f), 1.f);
        rxp0 = pack2f(rx, rx); ryp0 = pack2f(ry, ry);
        px = end_pos[(pedbase + b1r) * 2 + 0]; py = end_pos[(pedbase + b1r) * 2 + 1];
        rx = fminf(fmaxf(px - pax, -1.f), 1.f);
        ry = fminf(fmaxf(py - pay, -1.f), 1.f);
        rxp1 = pack2f(rx, rx); ryp1 = pack2f(ry, ry);
    }
    const uint32_t gOff0 = OFF_G + b0r * 288;
    const uint32_t gOff1 = OFF_G + b1r * 288;

    // B ldmatrix lane addressing
    const int bRow   = wn * 64 + (lane & 7) + ((lane >> 4) & 1) * 8;
    const int bKhalf = (lane >> 3) & 1;
    const int kq2    = (lane & 3) * 2;           // A-fragment k pair base

    float c[8][4];
    #pragma unroll
    for (int nt = 0; nt < 8; nt++)
        #pragma unroll
        for (int q = 0; q < 4; q++) c[nt][q] = 0.f;

    // prologue
    stage_chunk(0, sb, t, n0, pedbase);
    CP_COMMIT(); CP_WAIT0();
    __syncthreads();

    for (int ch = 0; ch < NCHUNK; ch++) {
        const int buf = ch & 1;
        const uint32_t tb = sb + buf * BUF_STRIDE;

        if (ch + 1 < NCHUNK) {
            stage_chunk((ch + 1) * BK, sb + (buf ^ 1) * BUF_STRIDE, t, n0, pedbase);
            CP_COMMIT();
        }

        #pragma unroll
        for (int s = 0; s < 4; s++) {
            const int kk = s * 16 + kq2;          // local k (floats) 0..63
            // M pairs (packed u64 loads)
            unsigned long long m0a = lds_u64(tb + OFF_M + kk * 4);
            unsigned long long m0b = lds_u64(tb + OFF_M + kk * 4 + 32);
            unsigned long long m1a = lds_u64(tb + OFF_M + 288 + kk * 4);
            unsigned long long m1b = lds_u64(tb + OFF_M + 288 + kk * 4 + 32);

            // B fragments (hi only)
            uint32_t bh[4][4];
            const int kbB = s * 32 + bKhalf * 16;
            #pragma unroll
            for (int p = 0; p < 4; p++) {
                int row = bRow + p * 16;
                ldsm4(bh[p], tb + row * 128 + (kbB ^ ((row & 7) << 4)));
            }

            // A fragments built in registers (single fp16)
            unsigned long long g0a = lds_u64(tb + gOff0 + kk * 4);
            unsigned long long g1a = lds_u64(tb + gOff1 + kk * 4);
            unsigned long long g0b = lds_u64(tb + gOff0 + kk * 4 + 32);
            unsigned long long g1b = lds_u64(tb + gOff1 + kk * 4 + 32);
            uint32_t ah[4];
            ah[0] = mk_fragh(m0a, m1a, g0a, rxp0, ryp0);
            ah[1] = mk_fragh(m0a, m1a, g1a, rxp1, ryp1);
            ah[2] = mk_fragh(m0b, m1b, g0b, rxp0, ryp0);
            ah[3] = mk_fragh(m0b, m1b, g1b, rxp1, ryp1);

            #pragma unroll
            for (int nt = 0; nt < 8; nt++)
                mma16816(c[nt], ah, &bh[nt >> 1][(nt & 1) * 2]);
        }

        if (ch + 1 < NCHUNK) {
            CP_WAIT0();
            __syncthreads();
        }
    }

    // ---- epilogue ----
    // warp-local max over its 16 b-rows, then cross-warp pair via smem
    float* red = (float*)smem;          // [4][128] floats, reuses buffer 0
    #pragma unroll
    for (int nt = 0; nt < 8; nt++) {
        #pragma unroll
        for (int j = 0; j < 2; j++) {
            float m = fmaxf(c[nt][j], c[nt][j + 2]);
            m = fmaxf(m, __shfl_xor_sync(0xffffffffu, m, 4));
            m = fmaxf(m, __shfl_xor_sync(0xffffffffu, m, 8));
            m = fmaxf(m, __shfl_xor_sync(0xffffffffu, m, 16));
            if (lane < 4)
                red[wm * 128 + wn * 64 + nt * 8 + lane * 2 + j] = m;
        }
    }
    __syncthreads();
    {
        const int a_local = t >> 7;          // 0..1
        const int col = t & 127;
        float m = fmaxf(red[(a_local * 2) * 128 + col],
                        red[(a_local * 2 + 1) * 128 + col]);
        const int ped = blockIdx.y * 2 + a_local;
        const int n = n0 + col;
        out[(size_t)ped * BOT_ + n] = fmaxf(m + b2[n], 0.f);
    }
}

// ---------------------------------------------------------------------------
extern "C" void kernel_launch(void* const* d_in, const int* in_sizes, int n_in,
                              void* d_out, int out_size) {
    const float* h_states = (const float*)d_in[0];
    const float* end_pos  = (const float*)d_in[1];
    const float* W_sp = (const float*)d_in[4];
    const float* b_sp = (const float*)d_in[5];
    const float* W1   = (const float*)d_in[6];
    const float* b1   = (const float*)d_in[7];
    const float* W2   = (const float*)d_in[8];
    const float* b2   = (const float*)d_in[9];
    float* out = (float*)d_out;

    cudaFuncSetAttribute(kern_main_mma, cudaFuncAttributeMaxDynamicSharedMemorySize, SMEM_BYTES);

    kern_M<<<D1_ / 256, 256>>>(W_sp, W1);
    kern_G<<<dim3(D1_ / 256, B_ / 8), 256>>>(h_states, b_sp, W1, b1);
    kern_W2T<<<dim3(BOT_ / 32, D1_ / 32), dim3(32, 8)>>>(W2);
    kern_main_mma<<<dim3(BOT_ / BN, RTOT / BM), 256, SMEM_BYTES>>>(end_pos, b2, out);
}

// round 15
// speedup vs baseline: 2.3954x; 1.2718x over previous
#include <cuda_runtime.h>
#include <cuda_fp16.h>
#include <cstdint>

// Problem constants
#define S_   16
#define P_   32
#define B_   512
#define H_   64
#define D1_  8192
#define BOT_ 1024
#define RTOT (S_*P_*P_)

// GEMM-2 tiling
#define BM   64
#define BN   128
#define BK   64
#define NCHUNK (D1_/BK)     // 128

// ---------------- device scratch (allocation-free) ----------------
__device__ __align__(256) __half g_Gh[B_ * D1_];      // 8 MB fp16
__device__ __align__(256) __half g_Mh[2 * D1_];
__device__ __align__(256) __half g_W2T_h[BOT_ * D1_]; // W2^T fp16  [n][k]

// ---------------- PTX helpers ----------------
__device__ __forceinline__ uint32_t smem_u32(const void* p) {
    uint32_t a;
    asm("{ .reg .u64 t; cvta.to.shared.u64 t, %1; cvt.u32.u64 %0, t; }" : "=r"(a) : "l"(p));
    return a;
}
__device__ __forceinline__ void mma16816(float* c, const uint32_t* a, const uint32_t* b) {
    asm volatile(
        "mma.sync.aligned.m16n8k16.row.col.f32.f16.f16.f32 "
        "{%0,%1,%2,%3}, {%4,%5,%6,%7}, {%8,%9}, {%0,%1,%2,%3};"
        : "+f"(c[0]), "+f"(c[1]), "+f"(c[2]), "+f"(c[3])
        : "r"(a[0]), "r"(a[1]), "r"(a[2]), "r"(a[3]), "r"(b[0]), "r"(b[1]));
}
__device__ __forceinline__ void ldsm4(uint32_t* r, uint32_t addr) {
    asm volatile("ldmatrix.sync.aligned.m8n8.x4.shared.b16 {%0,%1,%2,%3}, [%4];"
        : "=r"(r[0]), "=r"(r[1]), "=r"(r[2]), "=r"(r[3]) : "r"(addr));
}
#define CP16(dst, src) asm volatile("cp.async.cg.shared.global [%0], [%1], 16;" :: "r"(dst), "l"(src))
#define CP_COMMIT()    asm volatile("cp.async.commit_group;")
#define CP_WAIT0()     asm volatile("cp.async.wait_group 0;")

__device__ __forceinline__ uint32_t lds_u32(uint32_t addr) {
    uint32_t v;
    asm volatile("ld.shared.b32 %0, [%1];" : "=r"(v) : "r"(addr));
    return v;
}

// half2 A-fragment build: relu(rx*M0 + ry*M1 + G), all fp16 arithmetic
__device__ __forceinline__ uint32_t mk_h(uint32_t g, uint32_t m0, uint32_t m1,
                                         uint32_t rx2, uint32_t ry2) {
    __half2 acc = *(__half2*)&g;
    acc = __hfma2(*(__half2*)&ry2, *(__half2*)&m1, acc);
    acc = __hfma2(*(__half2*)&rx2, *(__half2*)&m0, acc);
    const __half2 z = __float2half2_rn(0.f);
    acc = __hmax2(acc, z);
    return *(uint32_t*)&acc;
}

// ---------------- Prep kernels ----------------
__global__ __launch_bounds__(256) void kern_M(const float* __restrict__ Wsp,
                                              const float* __restrict__ W1) {
    int d = blockIdx.x * 256 + threadIdx.x;
    float m0 = 0.f, m1 = 0.f;
    #pragma unroll 8
    for (int j = 0; j < 64; j++) {
        float w = W1[j * D1_ + d];
        m0 = fmaf(Wsp[j],      w, m0);
        m1 = fmaf(Wsp[64 + j], w, m1);
    }
    g_Mh[d]       = __float2half_rn(m0);
    g_Mh[D1_ + d] = __float2half_rn(m1);
}

__global__ __launch_bounds__(256) void kern_G(const float* __restrict__ h,
                                              const float* __restrict__ b_sp,
                                              const float* __restrict__ W1,
                                              const float* __restrict__ b1) {
    __shared__ float xs[8][128];
    const int tid  = threadIdx.x;
    const int col  = blockIdx.x * 256 + tid;
    const int row0 = blockIdx.y * 8;
    for (int e = tid; e < 8 * 128; e += 256) {
        int rr = e >> 7, j = e & 127;
        xs[rr][j] = (j < 64) ? b_sp[j] : h[(row0 + rr) * H_ + (j - 64)];
    }
    __syncthreads();
    float acc[8];
    float bb = b1[col];
    #pragma unroll
    for (int r = 0; r < 8; r++) acc[r] = bb;
    #pragma unroll 4
    for (int k = 0; k < 128; k++) {
        float w = W1[k * D1_ + col];
        #pragma unroll
        for (int r = 0; r < 8; r++) acc[r] = fmaf(xs[r][k], w, acc[r]);
    }
    #pragma unroll
    for (int r = 0; r < 8; r++)
        g_Gh[(row0 + r) * D1_ + col] = __float2half_rn(acc[r]);
}

// W2 [8192,1024] fp32 -> W2^T fp16 [1024,8192]
__global__ __launch_bounds__(256) void kern_W2T(const float* __restrict__ W2) {
    __shared__ float tile[32][33];
    const int tx = threadIdx.x, ty = threadIdx.y;
    const int n0 = blockIdx.x * 32, k0 = blockIdx.y * 32;
    #pragma unroll
    for (int r = 0; r < 4; r++)
        tile[ty + r * 8][tx] = W2[(k0 + ty + r * 8) * BOT_ + n0 + tx];
    __syncthreads();
    #pragma unroll
    for (int r = 0; r < 4; r++) {
        float v = tile[tx][ty + r * 8];
        g_W2T_h[(n0 + ty + r * 8) * D1_ + k0 + tx] = __float2half_rn(v);
    }
}

// ---------------- Main kernel ----------------
// Per buffer: Bh 16K | G 32x144B (4608) | M 2x144B (288)  -> 21504 B
#define OFF_G     16384
#define OFF_M     20992
#define BUF_STRIDE 21504
#define SMEM_BYTES (2 * BUF_STRIDE)   // 43008

__device__ __forceinline__ void stage_chunk(int k0, uint32_t tb, int t, int n0,
                                            int pedbase) {
    // B: 128 n-rows x 8 x 16B (SW128 swizzle on 128B rows)
    #pragma unroll
    for (int i = 0; i < 4; i++) {
        int idx = t + i * 256;
        int n = idx >> 3, seg = idx & 7;
        int sw = n * 128 + ((seg * 16) ^ ((n & 7) << 4));
        CP16(tb + sw, g_W2T_h + (size_t)(n0 + n) * D1_ + k0 + seg * 8);
    }
    // G fp16: 32 b-rows x 8 x 16B into 144B-stride rows (1 op per thread)
    {
        int b = t >> 3, seg = t & 7;
        CP16(tb + OFF_G + b * 144 + seg * 16,
             g_Gh + (size_t)(pedbase + b) * D1_ + k0 + seg * 8);
    }
    // M fp16: 2 x 64 halves
    if (t < 16) {
        int half = t >> 3, seg = t & 7;
        CP16(tb + OFF_M + half * 144 + seg * 16, g_Mh + half * D1_ + k0 + seg * 8);
    }
}

__global__ __launch_bounds__(256, 2)
void kern_main_mma(const float* __restrict__ end_pos,
                   const float* __restrict__ b2,
                   float* __restrict__ out) {
    extern __shared__ __align__(1024) char smem[];
    const uint32_t sb = smem_u32(smem);
    const int t = threadIdx.x;
    const int lane = t & 31, wid = t >> 5;
    const int wm = wid >> 1, wn = wid & 1;        // 4 m-warps x 2 n-warps
    const int n0 = blockIdx.x * BN;
    const int r0 = blockIdx.y * BM;
    const int pedbase = (r0 >> 10) << 5;          // scene * 32

    // per-thread rel-pos: warp rows = wm*16..+15; b = (wm&1)*16 + g4 (+8)
    const int a_idx = ((blockIdx.y * 2) & 31) + (wm >> 1);
    const float pax = end_pos[(pedbase + a_idx) * 2 + 0];
    const float pay = end_pos[(pedbase + a_idx) * 2 + 1];
    const int g4 = lane >> 2;
    const int b0r = (wm & 1) * 16 + g4;
    const int b1r = b0r + 8;
    uint32_t rx20, ry20, rx21, ry21;
    {
        float px = end_pos[(pedbase + b0r) * 2 + 0], py = end_pos[(pedbase + b0r) * 2 + 1];
        __half2 h;
        h = __float2half2_rn(fminf(fmaxf(px - pax, -1.f), 1.f)); rx20 = *(uint32_t*)&h;
        h = __float2half2_rn(fminf(fmaxf(py - pay, -1.f), 1.f)); ry20 = *(uint32_t*)&h;
        px = end_pos[(pedbase + b1r) * 2 + 0]; py = end_pos[(pedbase + b1r) * 2 + 1];
        h = __float2half2_rn(fminf(fmaxf(px - pax, -1.f), 1.f)); rx21 = *(uint32_t*)&h;
        h = __float2half2_rn(fminf(fmaxf(py - pay, -1.f), 1.f)); ry21 = *(uint32_t*)&h;
    }
    const uint32_t gOff0 = OFF_G + b0r * 144;
    const uint32_t gOff1 = OFF_G + b1r * 144;

    // B ldmatrix lane addressing
    const int bRow   = wn * 64 + (lane & 7) + ((lane >> 4) & 1) * 8;
    const int bKhalf = (lane >> 3) & 1;
    const int kq2    = (lane & 3) * 2;           // A-fragment k pair base (halves)

    float c[8][4];
    #pragma unroll
    for (int nt = 0; nt < 8; nt++)
        #pragma unroll
        for (int q = 0; q < 4; q++) c[nt][q] = 0.f;

    // prologue
    stage_chunk(0, sb, t, n0, pedbase);
    CP_COMMIT(); CP_WAIT0();
    __syncthreads();

    for (int ch = 0; ch < NCHUNK; ch++) {
        const int buf = ch & 1;
        const uint32_t tb = sb + buf * BUF_STRIDE;

        if (ch + 1 < NCHUNK) {
            stage_chunk((ch + 1) * BK, sb + (buf ^ 1) * BUF_STRIDE, t, n0, pedbase);
            CP_COMMIT();
        }

        #pragma unroll
        for (int s = 0; s < 4; s++) {
            const int kk = s * 16 + kq2;          // local k (halves) 0..63
            const uint32_t kb = kk * 2;           // byte offset within row

            // M pairs (u32 = 2 halves), k and k+8
            uint32_t m0a = lds_u32(tb + OFF_M + kb);
            uint32_t m0b = lds_u32(tb + OFF_M + kb + 16);
            uint32_t m1a = lds_u32(tb + OFF_M + 144 + kb);
            uint32_t m1b = lds_u32(tb + OFF_M + 144 + kb + 16);

            // B fragments
            uint32_t bh[4][4];
            const int kbB = s * 32 + bKhalf * 16;
            #pragma unroll
            for (int p = 0; p < 4; p++) {
                int row = bRow + p * 16;
                ldsm4(bh[p], tb + row * 128 + (kbB ^ ((row & 7) << 4)));
            }

            // A fragments: half2 build from fp16 G
            uint32_t g0a = lds_u32(tb + gOff0 + kb);
            uint32_t g1a = lds_u32(tb + gOff1 + kb);
            uint32_t g0b = lds_u32(tb + gOff0 + kb + 16);
            uint32_t g1b = lds_u32(tb + gOff1 + kb + 16);
            uint32_t ah[4];
            ah[0] = mk_h(g0a, m0a, m1a, rx20, ry20);
            ah[1] = mk_h(g1a, m0a, m1a, rx21, ry21);
            ah[2] = mk_h(g0b, m0b, m1b, rx20, ry20);
            ah[3] = mk_h(g1b, m0b, m1b, rx21, ry21);

            #pragma unroll
            for (int nt = 0; nt < 8; nt++)
                mma16816(c[nt], ah, &bh[nt >> 1][(nt & 1) * 2]);
        }

        if (ch + 1 < NCHUNK) {
            CP_WAIT0();
            __syncthreads();
        }
    }

    // ---- epilogue ----
    float* red = (float*)smem;          // [4][128] floats, reuses buffer 0
    #pragma unroll
    for (int nt = 0; nt < 8; nt++) {
        #pragma unroll
        for (int j = 0; j < 2; j++) {
            float m = fmaxf(c[nt][j], c[nt][j + 2]);
            m = fmaxf(m, __shfl_xor_sync(0xffffffffu, m, 4));
            m = fmaxf(m, __shfl_xor_sync(0xffffffffu, m, 8));
            m = fmaxf(m, __shfl_xor_sync(0xffffffffu, m, 16));
            if (lane < 4)
                red[wm * 128 + wn * 64 + nt * 8 + lane * 2 + j] = m;
        }
    }
    __syncthreads();
    {
        const int a_local = t >> 7;          // 0..1
        const int col = t & 127;
        float m = fmaxf(red[(a_local * 2) * 128 + col],
                        red[(a_local * 2 + 1) * 128 + col]);
        const int ped = blockIdx.y * 2 + a_local;
        const int n = n0 + col;
        out[(size_t)ped * BOT_ + n] = fmaxf(m + b2[n], 0.f);
    }
}

// ---------------------------------------------------------------------------
extern "C" void kernel_launch(void* const* d_in, const int* in_sizes, int n_in,
                              void* d_out, int out_size) {
    const float* h_states = (const float*)d_in[0];
    const float* end_pos  = (const float*)d_in[1];
    const float* W_sp = (const float*)d_in[4];
    const float* b_sp = (const float*)d_in[5];
    const float* W1   = (const float*)d_in[6];
    const float* b1   = (const float*)d_in[7];
    const float* W2   = (const float*)d_in[8];
    const float* b2   = (const float*)d_in[9];
    float* out = (float*)d_out;

    cudaFuncSetAttribute(kern_main_mma, cudaFuncAttributeMaxDynamicSharedMemorySize, SMEM_BYTES);

    kern_M<<<D1_ / 256, 256>>>(W_sp, W1);
    kern_G<<<dim3(D1_ / 256, B_ / 8), 256>>>(h_states, b_sp, W1, b1);
    kern_W2T<<<dim3(BOT_ / 32, D1_ / 32), dim3(32, 8)>>>(W2);
    kern_main_mma<<<dim3(BOT_ / BN, RTOT / BM), 256, SMEM_BYTES>>>(end_pos, b2, out);
}

// round 16
// speedup vs baseline: 2.4895x; 1.0393x over previous
#include <cuda_runtime.h>
#include <cuda_fp16.h>
#include <cstdint>

// Problem constants
#define S_   16
#define P_   32
#define B_   512
#define H_   64
#define D1_  8192
#define BOT_ 1024
#define RTOT (S_*P_*P_)

// GEMM-2 tiling: BM=128 (4 a-groups x 32 b), BN=64, 4 m-warps x 2 n-warps
#define BM   128
#define BN   64
#define BK   64
#define NCHUNK (D1_/BK)     // 128

// ---------------- device scratch (allocation-free) ----------------
__device__ __align__(256) __half g_Gh[B_ * D1_];      // 8 MB fp16
__device__ __align__(256) __half g_Mh[2 * D1_];
__device__ __align__(256) __half g_W2T_h[BOT_ * D1_]; // W2^T fp16  [n][k]

// ---------------- PTX helpers ----------------
__device__ __forceinline__ uint32_t smem_u32(const void* p) {
    uint32_t a;
    asm("{ .reg .u64 t; cvta.to.shared.u64 t, %1; cvt.u32.u64 %0, t; }" : "=r"(a) : "l"(p));
    return a;
}
__device__ __forceinline__ void mma16816(float* c, const uint32_t* a, const uint32_t* b) {
    asm volatile(
        "mma.sync.aligned.m16n8k16.row.col.f32.f16.f16.f32 "
        "{%0,%1,%2,%3}, {%4,%5,%6,%7}, {%8,%9}, {%0,%1,%2,%3};"
        : "+f"(c[0]), "+f"(c[1]), "+f"(c[2]), "+f"(c[3])
        : "r"(a[0]), "r"(a[1]), "r"(a[2]), "r"(a[3]), "r"(b[0]), "r"(b[1]));
}
__device__ __forceinline__ void ldsm4(uint32_t* r, uint32_t addr) {
    asm volatile("ldmatrix.sync.aligned.m8n8.x4.shared.b16 {%0,%1,%2,%3}, [%4];"
        : "=r"(r[0]), "=r"(r[1]), "=r"(r[2]), "=r"(r[3]) : "r"(addr));
}
#define CP16(dst, src) asm volatile("cp.async.cg.shared.global [%0], [%1], 16;" :: "r"(dst), "l"(src))
#define CP_COMMIT()    asm volatile("cp.async.commit_group;")
#define CP_WAIT0()     asm volatile("cp.async.wait_group 0;")

__device__ __forceinline__ uint32_t lds_u32(uint32_t addr) {
    uint32_t v;
    asm volatile("ld.shared.b32 %0, [%1];" : "=r"(v) : "r"(addr));
    return v;
}

// half2 A-fragment build: relu(rx*M0 + ry*M1 + G), all fp16 arithmetic
__device__ __forceinline__ uint32_t mk_h(uint32_t g, uint32_t m0, uint32_t m1,
                                         uint32_t rx2, uint32_t ry2) {
    __half2 acc = *(__half2*)&g;
    acc = __hfma2(*(__half2*)&ry2, *(__half2*)&m1, acc);
    acc = __hfma2(*(__half2*)&rx2, *(__half2*)&m0, acc);
    const __half2 z = __float2half2_rn(0.f);
    acc = __hmax2(acc, z);
    return *(uint32_t*)&acc;
}

// ---------------- Prep kernels ----------------
__global__ __launch_bounds__(256) void kern_M(const float* __restrict__ Wsp,
                                              const float* __restrict__ W1) {
    int d = blockIdx.x * 256 + threadIdx.x;
    float m0 = 0.f, m1 = 0.f;
    #pragma unroll 8
    for (int j = 0; j < 64; j++) {
        float w = W1[j * D1_ + d];
        m0 = fmaf(Wsp[j],      w, m0);
        m1 = fmaf(Wsp[64 + j], w, m1);
    }
    g_Mh[d]       = __float2half_rn(m0);
    g_Mh[D1_ + d] = __float2half_rn(m1);
}

__global__ __launch_bounds__(256) void kern_G(const float* __restrict__ h,
                                              const float* __restrict__ b_sp,
                                              const float* __restrict__ W1,
                                              const float* __restrict__ b1) {
    __shared__ float xs[8][128];
    const int tid  = threadIdx.x;
    const int col  = blockIdx.x * 256 + tid;
    const int row0 = blockIdx.y * 8;
    for (int e = tid; e < 8 * 128; e += 256) {
        int rr = e >> 7, j = e & 127;
        xs[rr][j] = (j < 64) ? b_sp[j] : h[(row0 + rr) * H_ + (j - 64)];
    }
    __syncthreads();
    float acc[8];
    float bb = b1[col];
    #pragma unroll
    for (int r = 0; r < 8; r++) acc[r] = bb;
    #pragma unroll 4
    for (int k = 0; k < 128; k++) {
        float w = W1[k * D1_ + col];
        #pragma unroll
        for (int r = 0; r < 8; r++) acc[r] = fmaf(xs[r][k], w, acc[r]);
    }
    #pragma unroll
    for (int r = 0; r < 8; r++)
        g_Gh[(row0 + r) * D1_ + col] = __float2half_rn(acc[r]);
}

// W2 [8192,1024] fp32 -> W2^T fp16 [1024,8192]
__global__ __launch_bounds__(256) void kern_W2T(const float* __restrict__ W2) {
    __shared__ float tile[32][33];
    const int tx = threadIdx.x, ty = threadIdx.y;
    const int n0 = blockIdx.x * 32, k0 = blockIdx.y * 32;
    #pragma unroll
    for (int r = 0; r < 4; r++)
        tile[ty + r * 8][tx] = W2[(k0 + ty + r * 8) * BOT_ + n0 + tx];
    __syncthreads();
    #pragma unroll
    for (int r = 0; r < 4; r++) {
        float v = tile[tx][ty + r * 8];
        g_W2T_h[(n0 + ty + r * 8) * D1_ + k0 + tx] = __float2half_rn(v);
    }
}

// ---------------- Main kernel ----------------
// Per buffer: B 8K | G 32x144B (4608) | M 2x144B (288)  -> 13312 B
#define OFF_G     8192
#define OFF_M     12800
#define BUF_STRIDE 13312
#define SMEM_BYTES (2 * BUF_STRIDE)   // 26624

__device__ __forceinline__ void stage_chunk(int k0, uint32_t tb, int t, int n0,
                                            int pedbase) {
    // B: 64 n-rows x 8 x 16B (SW128 swizzle on 128B rows) -> 2 ops/thread
    #pragma unroll
    for (int i = 0; i < 2; i++) {
        int idx = t + i * 256;
        int n = idx >> 3, seg = idx & 7;
        int sw = n * 128 + ((seg * 16) ^ ((n & 7) << 4));
        CP16(tb + sw, g_W2T_h + (size_t)(n0 + n) * D1_ + k0 + seg * 8);
    }
    // G fp16: 32 b-rows x 8 x 16B into 144B-stride rows (1 op/thread)
    {
        int b = t >> 3, seg = t & 7;
        CP16(tb + OFF_G + b * 144 + seg * 16,
             g_Gh + (size_t)(pedbase + b) * D1_ + k0 + seg * 8);
    }
    // M fp16: 2 x 64 halves
    if (t < 16) {
        int half = t >> 3, seg = t & 7;
        CP16(tb + OFF_M + half * 144 + seg * 16, g_Mh + half * D1_ + k0 + seg * 8);
    }
}

__global__ __launch_bounds__(256, 2)
void kern_main_mma(const float* __restrict__ end_pos,
                   const float* __restrict__ b2,
                   float* __restrict__ out) {
    extern __shared__ __align__(1024) char smem[];
    const uint32_t sb = smem_u32(smem);
    const int t = threadIdx.x;
    const int lane = t & 31, wid = t >> 5;
    const int wm = wid >> 1, wn = wid & 1;        // 4 m-warps x 2 n-warps
    const int n0 = blockIdx.x * BN;
    const int by = blockIdx.y;
    const int pedbase = (by >> 3) << 5;           // scene * 32 (8 by per scene)

    // warp owns one a-group: a = (by&7)*4 + wm; its 32 rows = all b of the scene
    const int a_idx = ((by & 7) << 2) + wm;
    const float pax = end_pos[(pedbase + a_idx) * 2 + 0];
    const float pay = end_pos[(pedbase + a_idx) * 2 + 1];
    const int g4 = lane >> 2;

    // 4 b-rows per thread: b = mt*16 + h*8 + g4  (mt,h in {0,1})
    uint32_t rx2[2][2], ry2[2][2];
    uint32_t gO[2][2];
    #pragma unroll
    for (int mt = 0; mt < 2; mt++)
        #pragma unroll
        for (int h = 0; h < 2; h++) {
            int b = mt * 16 + h * 8 + g4;
            float px = end_pos[(pedbase + b) * 2 + 0];
            float py = end_pos[(pedbase + b) * 2 + 1];
            __half2 hh;
            hh = __float2half2_rn(fminf(fmaxf(px - pax, -1.f), 1.f));
            rx2[mt][h] = *(uint32_t*)&hh;
            hh = __float2half2_rn(fminf(fmaxf(py - pay, -1.f), 1.f));
            ry2[mt][h] = *(uint32_t*)&hh;
            gO[mt][h] = OFF_G + b * 144;
        }

    // B ldmatrix lane addressing: warp n-cols = wn*32..+31
    const int bRow   = wn * 32 + (lane & 7) + ((lane >> 4) & 1) * 8;
    const int bKhalf = (lane >> 3) & 1;
    const int kq2    = (lane & 3) * 2;           // A-fragment k pair base (halves)

    float c[2][4][4];
    #pragma unroll
    for (int mt = 0; mt < 2; mt++)
        #pragma unroll
        for (int nt = 0; nt < 4; nt++)
            #pragma unroll
            for (int q = 0; q < 4; q++) c[mt][nt][q] = 0.f;

    // prologue
    stage_chunk(0, sb, t, n0, pedbase);
    CP_COMMIT(); CP_WAIT0();
    __syncthreads();

    for (int ch = 0; ch < NCHUNK; ch++) {
        const int buf = ch & 1;
        const uint32_t tb = sb + buf * BUF_STRIDE;

        if (ch + 1 < NCHUNK) {
            stage_chunk((ch + 1) * BK, sb + (buf ^ 1) * BUF_STRIDE, t, n0, pedbase);
            CP_COMMIT();
        }

        #pragma unroll
        for (int s = 0; s < 4; s++) {
            const int kk = s * 16 + kq2;          // local k (halves) 0..63
            const uint32_t kb = kk * 2;           // byte offset within row

            // M pairs (u32 = 2 halves), k and k+8
            uint32_t m0a = lds_u32(tb + OFF_M + kb);
            uint32_t m0b = lds_u32(tb + OFF_M + kb + 16);
            uint32_t m1a = lds_u32(tb + OFF_M + 144 + kb);
            uint32_t m1b = lds_u32(tb + OFF_M + 144 + kb + 16);

            // B fragments: 2 ldsm4 (32 cols)
            uint32_t bh[2][4];
            const int kbB = s * 32 + bKhalf * 16;
            #pragma unroll
            for (int p = 0; p < 2; p++) {
                int row = bRow + p * 16;
                ldsm4(bh[p], tb + row * 128 + (kbB ^ ((row & 7) << 4)));
            }

            // A fragments: 2 m-tiles x 4, half2 build from fp16 G
            uint32_t ah[2][4];
            #pragma unroll
            for (int mt = 0; mt < 2; mt++) {
                uint32_t g0a = lds_u32(tb + gO[mt][0] + kb);
                uint32_t g1a = lds_u32(tb + gO[mt][1] + kb);
                uint32_t g0b = lds_u32(tb + gO[mt][0] + kb + 16);
                uint32_t g1b = lds_u32(tb + gO[mt][1] + kb + 16);
                ah[mt][0] = mk_h(g0a, m0a, m1a, rx2[mt][0], ry2[mt][0]);
                ah[mt][1] = mk_h(g1a, m0a, m1a, rx2[mt][1], ry2[mt][1]);
                ah[mt][2] = mk_h(g0b, m0b, m1b, rx2[mt][0], ry2[mt][0]);
                ah[mt][3] = mk_h(g1b, m0b, m1b, rx2[mt][1], ry2[mt][1]);
            }

            #pragma unroll
            for (int mt = 0; mt < 2; mt++)
                #pragma unroll
                for (int nt = 0; nt < 4; nt++)
                    mma16816(c[mt][nt], ah[mt], &bh[nt >> 1][(nt & 1) * 2]);
        }

        if (ch + 1 < NCHUNK) {
            CP_WAIT0();
            __syncthreads();
        }
    }

    // ---- epilogue: warp-local (all 32 b in-warp) ----
    // max over mt & quad-rows, then shfl over g4; direct store, no smem
    const int ped = pedbase + a_idx;
    const int cq = lane & 3;
    float* orow = out + (size_t)ped * BOT_ + n0 + wn * 32;
    const float* b2p = b2 + n0 + wn * 32;
    #pragma unroll
    for (int nt = 0; nt < 4; nt++) {
        #pragma unroll
        for (int j = 0; j < 2; j++) {
            float m = fmaxf(fmaxf(c[0][nt][j], c[0][nt][j + 2]),
                            fmaxf(c[1][nt][j], c[1][nt][j + 2]));
            m = fmaxf(m, __shfl_xor_sync(0xffffffffu, m, 4));
            m = fmaxf(m, __shfl_xor_sync(0xffffffffu, m, 8));
            m = fmaxf(m, __shfl_xor_sync(0xffffffffu, m, 16));
            if (lane < 4) {
                int n = nt * 8 + cq * 2 + j;
                orow[n] = fmaxf(m + b2p[n], 0.f);
            }
        }
    }
}

// ---------------------------------------------------------------------------
extern "C" void kernel_launch(void* const* d_in, const int* in_sizes, int n_in,
                              void* d_out, int out_size) {
    const float* h_states = (const float*)d_in[0];
    const float* end_pos  = (const float*)d_in[1];
    const float* W_sp = (const float*)d_in[4];
    const float* b_sp = (const float*)d_in[5];
    const float* W1   = (const float*)d_in[6];
    const float* b1   = (const float*)d_in[7];
    const float* W2   = (const float*)d_in[8];
    const float* b2   = (const float*)d_in[9];
    float* out = (float*)d_out;

    cudaFuncSetAttribute(kern_main_mma, cudaFuncAttributeMaxDynamicSharedMemorySize, SMEM_BYTES);

    kern_M<<<D1_ / 256, 256>>>(W_sp, W1);
    kern_G<<<dim3(D1_ / 256, B_ / 8), 256>>>(h_states, b_sp, W1, b1);
    kern_W2T<<<dim3(BOT_ / 32, D1_ / 32), dim3(32, 8)>>>(W2);
    kern_main_mma<<<dim3(BOT_ / BN, RTOT / BM), 256, SMEM_BYTES>>>(end_pos, b2, out);
}

// round 17
// speedup vs baseline: 2.7075x; 1.0875x over previous
#include <cuda_runtime.h>
#include <cuda_fp16.h>
#include <cstdint>

// Problem constants
#define S_   16
#define P_   32
#define B_   512
#define H_   64
#define D1_  8192
#define BOT_ 1024
#define RTOT (S_*P_*P_)

// GEMM-2 tiling: BM=128, BN=64, 128 threads = 2m x 2n warps, warp tile 64x32
#define BM   128
#define BN   64
#define BK   64
#define NCHUNK (D1_/BK)     // 128

// ---------------- device scratch (allocation-free) ----------------
__device__ __align__(256) __half g_Gh[B_ * D1_];      // 8 MB fp16
__device__ __align__(256) __half g_Mi[2 * D1_];       // M0/M1 k-pair interleaved
__device__ __align__(256) __half g_W2T_h[BOT_ * D1_]; // W2^T fp16  [n][k]

// ---------------- PTX helpers ----------------
__device__ __forceinline__ uint32_t smem_u32(const void* p) {
    uint32_t a;
    asm("{ .reg .u64 t; cvta.to.shared.u64 t, %1; cvt.u32.u64 %0, t; }" : "=r"(a) : "l"(p));
    return a;
}
__device__ __forceinline__ void mma16816(float* c, const uint32_t* a, const uint32_t* b) {
    asm volatile(
        "mma.sync.aligned.m16n8k16.row.col.f32.f16.f16.f32 "
        "{%0,%1,%2,%3}, {%4,%5,%6,%7}, {%8,%9}, {%0,%1,%2,%3};"
        : "+f"(c[0]), "+f"(c[1]), "+f"(c[2]), "+f"(c[3])
        : "r"(a[0]), "r"(a[1]), "r"(a[2]), "r"(a[3]), "r"(b[0]), "r"(b[1]));
}
__device__ __forceinline__ void ldsm4(uint32_t* r, uint32_t addr) {
    asm volatile("ldmatrix.sync.aligned.m8n8.x4.shared.b16 {%0,%1,%2,%3}, [%4];"
        : "=r"(r[0]), "=r"(r[1]), "=r"(r[2]), "=r"(r[3]) : "r"(addr));
}
#define CP16(dst, src) asm volatile("cp.async.cg.shared.global [%0], [%1], 16;" :: "r"(dst), "l"(src))
#define CP_COMMIT()    asm volatile("cp.async.commit_group;")
#define CP_WAIT0()     asm volatile("cp.async.wait_group 0;")

__device__ __forceinline__ void lds_u64v(uint32_t& a, uint32_t& b, uint32_t addr) {
    asm volatile("ld.shared.v2.b32 {%0,%1}, [%2];" : "=r"(a), "=r"(b) : "r"(addr));
}

// half2 A-fragment build: relu(rx*M0 + ry*M1 + G), all fp16 arithmetic
__device__ __forceinline__ uint32_t mk_h(uint32_t g, uint32_t m0, uint32_t m1,
                                         uint32_t rx2, uint32_t ry2) {
    __half2 acc = *(__half2*)&g;
    acc = __hfma2(*(__half2*)&ry2, *(__half2*)&m1, acc);
    acc = __hfma2(*(__half2*)&rx2, *(__half2*)&m0, acc);
    const __half2 z = __float2half2_rn(0.f);
    acc = __hmax2(acc, z);
    return *(uint32_t*)&acc;
}

// ---------------- Prep kernels ----------------
// M interleaved layout: for k-pair kp: [kp*4+0,1] = M0[2kp,2kp+1], [kp*4+2,3] = M1[2kp,2kp+1]
__global__ __launch_bounds__(256) void kern_M(const float* __restrict__ Wsp,
                                              const float* __restrict__ W1) {
    int d = blockIdx.x * 256 + threadIdx.x;
    float m0 = 0.f, m1 = 0.f;
    #pragma unroll 8
    for (int j = 0; j < 64; j++) {
        float w = W1[j * D1_ + d];
        m0 = fmaf(Wsp[j],      w, m0);
        m1 = fmaf(Wsp[64 + j], w, m1);
    }
    int kp = d >> 1, lo = d & 1;
    g_Mi[kp * 4 + lo]     = __float2half_rn(m0);
    g_Mi[kp * 4 + 2 + lo] = __float2half_rn(m1);
}

__global__ __launch_bounds__(256) void kern_G(const float* __restrict__ h,
                                              const float* __restrict__ b_sp,
                                              const float* __restrict__ W1,
                                              const float* __restrict__ b1) {
    __shared__ float xs[8][128];
    const int tid  = threadIdx.x;
    const int col  = blockIdx.x * 256 + tid;
    const int row0 = blockIdx.y * 8;
    for (int e = tid; e < 8 * 128; e += 256) {
        int rr = e >> 7, j = e & 127;
        xs[rr][j] = (j < 64) ? b_sp[j] : h[(row0 + rr) * H_ + (j - 64)];
    }
    __syncthreads();
    float acc[8];
    float bb = b1[col];
    #pragma unroll
    for (int r = 0; r < 8; r++) acc[r] = bb;
    #pragma unroll 4
    for (int k = 0; k < 128; k++) {
        float w = W1[k * D1_ + col];
        #pragma unroll
        for (int r = 0; r < 8; r++) acc[r] = fmaf(xs[r][k], w, acc[r]);
    }
    #pragma unroll
    for (int r = 0; r < 8; r++)
        g_Gh[(row0 + r) * D1_ + col] = __float2half_rn(acc[r]);
}

// W2 [8192,1024] fp32 -> W2^T fp16 [1024,8192]
__global__ __launch_bounds__(256) void kern_W2T(const float* __restrict__ W2) {
    __shared__ float tile[32][33];
    const int tx = threadIdx.x, ty = threadIdx.y;
    const int n0 = blockIdx.x * 32, k0 = blockIdx.y * 32;
    #pragma unroll
    for (int r = 0; r < 4; r++)
        tile[ty + r * 8][tx] = W2[(k0 + ty + r * 8) * BOT_ + n0 + tx];
    __syncthreads();
    #pragma unroll
    for (int r = 0; r < 4; r++) {
        float v = tile[tx][ty + r * 8];
        g_W2T_h[(n0 + ty + r * 8) * D1_ + k0 + tx] = __float2half_rn(v);
    }
}

// ---------------- Main kernel ----------------
// Per buffer: B 8K | G 32x144B (4608) | M 512B  -> 13312 B
#define OFF_G     8192
#define OFF_M     12800
#define BUF_STRIDE 13312
#define SMEM_BYTES (2 * BUF_STRIDE)   // 26624

__device__ __forceinline__ void stage_chunk(int k0, uint32_t tb, int t, int n0,
                                            int pedbase) {
    // B: 64 n-rows x 8 x 16B (SW128 swizzle on 128B rows) -> 4 ops/thread
    #pragma unroll
    for (int i = 0; i < 4; i++) {
        int idx = t + i * 128;
        int n = idx >> 3, seg = idx & 7;
        int sw = n * 128 + ((seg * 16) ^ ((n & 7) << 4));
        CP16(tb + sw, g_W2T_h + (size_t)(n0 + n) * D1_ + k0 + seg * 8);
    }
    // G fp16: 32 b-rows x 8 x 16B into 144B-stride rows -> 2 ops/thread
    #pragma unroll
    for (int i = 0; i < 2; i++) {
        int idx = t + i * 128;
        int b = idx >> 3, seg = idx & 7;
        CP16(tb + OFF_G + b * 144 + seg * 16,
             g_Gh + (size_t)(pedbase + b) * D1_ + k0 + seg * 8);
    }
    // M interleaved: 256B for this chunk (byte offset k0*4 in g_Mi)
    if (t < 16)
        CP16(tb + OFF_M + t * 16, (const char*)g_Mi + (size_t)k0 * 4 + t * 16);
}

__global__ __launch_bounds__(128, 4)
void kern_main_mma(const float* __restrict__ end_pos,
                   const float* __restrict__ b2,
                   float* __restrict__ out) {
    extern __shared__ __align__(1024) char smem[];
    const uint32_t sb = smem_u32(smem);
    const int t = threadIdx.x;
    const int lane = t & 31, wid = t >> 5;
    const int wm = wid >> 1, wn = wid & 1;        // 2 m-warps x 2 n-warps
    const int n0 = blockIdx.x * BN;
    const int by = blockIdx.y;
    const int pedbase = (by >> 3) << 5;           // scene * 32 (8 by per scene)
    const int abase = (by & 7) << 2;              // 4 a-groups per tile

    // warp owns a-pair {abase + wm*2, +1}; rows wm*64 + mt*16 (mt 0..3)
    const int g4 = lane >> 2;

    // (rx,ry) half2-broadcast for 2 a's x 4 b-rows (b = g4 + 8j)
    uint32_t rx2[2][4], ry2[2][4];
    #pragma unroll
    for (int at = 0; at < 2; at++) {
        int a_idx = abase + wm * 2 + at;
        float pax = end_pos[(pedbase + a_idx) * 2 + 0];
        float pay = end_pos[(pedbase + a_idx) * 2 + 1];
        #pragma unroll
        for (int j = 0; j < 4; j++) {
            int b = j * 8 + g4;
            float px = end_pos[(pedbase + b) * 2 + 0];
            float py = end_pos[(pedbase + b) * 2 + 1];
            __half2 hh;
            hh = __float2half2_rn(fminf(fmaxf(px - pax, -1.f), 1.f));
            rx2[at][j] = *(uint32_t*)&hh;
            hh = __float2half2_rn(fminf(fmaxf(py - pay, -1.f), 1.f));
            ry2[at][j] = *(uint32_t*)&hh;
        }
    }

    // G ldmatrix lane address pieces (fragment-layout tiles over 32 b-rows)
    const int gRow   = (lane & 7) + ((lane >> 3) & 1) * 8;   // + pair*16
    const int gKhalf = lane >> 4;                            // 16B within row
    // B ldmatrix lane addressing: warp n-cols = wn*32..+31
    const int bRow   = wn * 32 + (lane & 7) + ((lane >> 4) & 1) * 8;
    const int bKhalf = (lane >> 3) & 1;
    const int cq     = lane & 3;

    float c[4][4][4];
    #pragma unroll
    for (int mt = 0; mt < 4; mt++)
        #pragma unroll
        for (int nt = 0; nt < 4; nt++)
            #pragma unroll
            for (int q = 0; q < 4; q++) c[mt][nt][q] = 0.f;

    // prologue
    stage_chunk(0, sb, t, n0, pedbase);
    CP_COMMIT(); CP_WAIT0();
    __syncthreads();

    for (int ch = 0; ch < NCHUNK; ch++) {
        const uint32_t tb = sb + (ch & 1) * BUF_STRIDE;

        if (ch + 1 < NCHUNK) {
            stage_chunk((ch + 1) * BK, sb + ((ch & 1) ^ 1) * BUF_STRIDE, t, n0, pedbase);
            CP_COMMIT();
        }

        #pragma unroll
        for (int s = 0; s < 4; s++) {
            // M pairs: kp = s*8 + cq -> (m0 low, m1 low); +4 -> high half
            uint32_t m0a, m1a, m0b, m1b;
            lds_u64v(m0a, m1a, tb + OFF_M + (s * 8 + cq) * 8);
            lds_u64v(m0b, m1b, tb + OFF_M + (s * 8 + cq) * 8 + 32);

            // G fragments over the 32 b-rows (shared by both a's)
            uint32_t g0[4], g1[4];
            {
                uint32_t ga = tb + OFF_G + gRow * 144 + gKhalf * 16 + s * 32;
                ldsm4(g0, ga);                 // b-rows 0-15
                ldsm4(g1, ga + 16 * 144);      // b-rows 16-31
            }

            // B fragments (32 cols)
            uint32_t bh[2][4];
            const int kbB = s * 32 + bKhalf * 16;
            #pragma unroll
            for (int p = 0; p < 2; p++) {
                int row = bRow + p * 16;
                ldsm4(bh[p], tb + row * 128 + (kbB ^ ((row & 7) << 4)));
            }

            // 4 m-tiles: mt = at*2 + half; half selects g0/g1 (b 0-15 / 16-31)
            #pragma unroll
            for (int mt = 0; mt < 4; mt++) {
                const uint32_t* gl = (mt & 1) ? g1 : g0;
                const int at = mt >> 1;
                const int jb = (mt & 1) * 2;       // b-row index base (g4+jb*8)
                uint32_t ah[4];
                ah[0] = mk_h(gl[0], m0a, m1a, rx2[at][jb],     ry2[at][jb]);
                ah[1] = mk_h(gl[1], m0a, m1a, rx2[at][jb + 1], ry2[at][jb + 1]);
                ah[2] = mk_h(gl[2], m0b, m1b, rx2[at][jb],     ry2[at][jb]);
                ah[3] = mk_h(gl[3], m0b, m1b, rx2[at][jb + 1], ry2[at][jb + 1]);
                #pragma unroll
                for (int nt = 0; nt < 4; nt++)
                    mma16816(c[mt][nt], ah, &bh[nt >> 1][(nt & 1) * 2]);
            }
        }

        if (ch + 1 < NCHUNK) {
            CP_WAIT0();
            __syncthreads();
        }
    }

    // ---- epilogue: per a (at): max over its 2 m-tiles + quad rows, shfl over g4 ----
    #pragma unroll
    for (int at = 0; at < 2; at++) {
        const int ped = pedbase + abase + wm * 2 + at;
        float* orow = out + (size_t)ped * BOT_ + n0 + wn * 32;
        const float* b2p = b2 + n0 + wn * 32;
        #pragma unroll
        for (int nt = 0; nt < 4; nt++) {
            #pragma unroll
            for (int j = 0; j < 2; j++) {
                float m = fmaxf(fmaxf(c[at * 2][nt][j],     c[at * 2][nt][j + 2]),
                                fmaxf(c[at * 2 + 1][nt][j], c[at * 2 + 1][nt][j + 2]));
                m = fmaxf(m, __shfl_xor_sync(0xffffffffu, m, 4));
                m = fmaxf(m, __shfl_xor_sync(0xffffffffu, m, 8));
                m = fmaxf(m, __shfl_xor_sync(0xffffffffu, m, 16));
                if (lane < 4) {
                    int n = nt * 8 + cq * 2 + j;
                    orow[n] = fmaxf(m + b2p[n], 0.f);
                }
            }
        }
    }
}

// ---------------------------------------------------------------------------
extern "C" void kernel_launch(void* const* d_in, const int* in_sizes, int n_in,
                              void* d_out, int out_size) {
    const float* h_states = (const float*)d_in[0];
    const float* end_pos  = (const float*)d_in[1];
    const float* W_sp = (const float*)d_in[4];
    const float* b_sp = (const float*)d_in[5];
    const float* W1   = (const float*)d_in[6];
    const float* b1   = (const float*)d_in[7];
    const float* W2   = (const float*)d_in[8];
    const float* b2   = (const float*)d_in[9];
    float* out = (float*)d_out;

    cudaFuncSetAttribute(kern_main_mma, cudaFuncAttributeMaxDynamicSharedMemorySize, SMEM_BYTES);

    kern_M<<<D1_ / 256, 256>>>(W_sp, W1);
    kern_G<<<dim3(D1_ / 256, B_ / 8), 256>>>(h_states, b_sp, W1, b1);
    kern_W2T<<<dim3(BOT_ / 32, D1_ / 32), dim3(32, 8)>>>(W2);
    kern_main_mma<<<dim3(BOT_ / BN, RTOT / BM), 128, SMEM_BYTES>>>(end_pos, b2, out);
}